// round 8
// baseline (speedup 1.0000x reference)
#include <cuda_runtime.h>
#include <cuda_fp16.h>

#define NN 50000
#define NE 800000
#define TE (NE + NN)

typedef unsigned long long ull;

// ---- scratch (static device globals: no allocation allowed) ----
__device__ int   g_is64;
__device__ int   g_counts[NN];
__device__ int   g_offsets[NN];
__device__ int   g_cursor[NN];
__device__ int   g_bsum[128];
__device__ int   g_csr[TE];
__device__ uint2 g_h2[NN * 32];    // per-layer GEMM output, fp16x4 per lane-slot
__device__ float g_t0[NN * 128];   // layer-0 output (fp32)
__device__ float g_t1[NN * 128];   // layer-1 output (fp32)
__device__ float g_as[NN * 4];     // alpha_src per node per head (fp32, exact)
__device__ float g_ad[NN * 4];     // alpha_dst per node per head (fp32, exact)

// packed-f32x2 FMA: d.xy = a.xy * b.xy + d.xy  (Blackwell; PTX-only encoding)
__device__ __forceinline__ void ffma2(ull& d, ull a, ull b) {
    asm("fma.rn.f32x2 %0, %1, %2, %0;" : "+l"(d) : "l"(a), "l"(b));
}

// ================= edge-index dtype detection (parallel) =================
__global__ void k_detect(const int* __restrict__ ei32) {
    int v = ei32[2 * threadIdx.x + 1];
    unsigned nz = __ballot_sync(0xffffffffu, v != 0);
    __shared__ unsigned s[2];
    if ((threadIdx.x & 31) == 0) s[threadIdx.x >> 5] = nz;
    __syncthreads();
    if (threadIdx.x == 0) g_is64 = ((s[0] | s[1]) == 0u) ? 1 : 0;
}

__device__ __forceinline__ int edge_at(const int* ei32, long long idx) {
    return g_is64 ? ei32[2 * idx] : ei32[idx];
}

// ================= CSR construction =================

__global__ void k_zero() {
    int i = blockIdx.x * blockDim.x + threadIdx.x;
    if (i < NN) g_counts[i] = 0;
}

__global__ void k_hist(const int* __restrict__ ei32) {
    int i = blockIdx.x * blockDim.x + threadIdx.x;
    if (i >= TE) return;
    int d = (i < NE) ? edge_at(ei32, (long long)NE + i) : (i - NE);
    if ((unsigned)d < NN) atomicAdd(&g_counts[d], 1);
}

__global__ void k_scanA() {
    __shared__ int s[512];
    int i = blockIdx.x * 512 + threadIdx.x;
    int v = (i < NN) ? g_counts[i] : 0;
    s[threadIdx.x] = v;
    __syncthreads();
    for (int off = 1; off < 512; off <<= 1) {
        int t = (threadIdx.x >= off) ? s[threadIdx.x - off] : 0;
        __syncthreads();
        s[threadIdx.x] += t;
        __syncthreads();
    }
    if (i < NN) g_offsets[i] = s[threadIdx.x] - v;
    if (threadIdx.x == 511) g_bsum[blockIdx.x] = s[511];
}

__global__ void k_scanB(int nb) {
    __shared__ int s[128];
    int t = threadIdx.x;
    int v = (t < nb) ? g_bsum[t] : 0;
    s[t] = v;
    __syncthreads();
    for (int off = 1; off < 128; off <<= 1) {
        int u = (t >= off) ? s[t - off] : 0;
        __syncthreads();
        s[t] += u;
        __syncthreads();
    }
    if (t < nb) g_bsum[t] = s[t] - v;
}

__global__ void k_scanC() {
    int i = blockIdx.x * 512 + threadIdx.x;
    if (i < NN) {
        int o = g_offsets[i] + g_bsum[blockIdx.x];
        g_offsets[i] = o;
        g_cursor[i]  = o;
    }
}

__global__ void k_scatter(const int* __restrict__ ei32) {
    int i = blockIdx.x * blockDim.x + threadIdx.x;
    if (i >= TE) return;
    int srcn, dstn;
    if (i < NE) {
        srcn = edge_at(ei32, i);
        dstn = edge_at(ei32, (long long)NE + i);
    } else {
        srcn = dstn = i - NE;
    }
    if ((unsigned)dstn >= NN || (unsigned)srcn >= NN) return;
    int pos = atomicAdd(&g_cursor[dstn], 1);
    if ((unsigned)pos < TE) g_csr[pos] = srcn;
}

// ================= GEMM (packed f32x2) + fused attention coeffs =========

template <int HEADS, int XB>
__global__ __launch_bounds__(256) void k_gemm(
    const float* __restrict__ Xin, const float* __restrict__ W,
    const float* __restrict__ asr, const float* __restrict__ adr)
{
    const float* X = (XB == 0) ? Xin : (XB == 1 ? (const float*)g_t0 : (const float*)g_t1);
    __shared__ float sW[32 * 128];    // 16 KB
    __shared__ ull   sX2[64 * 32];    // 16 KB ({x,x} duplicated)
    int tid  = threadIdx.x;
    int warp = tid >> 5, lane = tid & 31;
    int rowBase = blockIdx.x * 64;

    ull acc2[8][2];
#pragma unroll
    for (int r = 0; r < 8; r++) { acc2[r][0] = 0ull; acc2[r][1] = 0ull; }

    for (int k0 = 0; k0 < 128; k0 += 32) {
        for (int idx = tid; idx < 1024; idx += 256)
            ((float4*)sW)[idx] = ((const float4*)(W + k0 * 128))[idx];
        for (int idx = tid; idx < 512; idx += 256) {
            int r = idx >> 3, kk = idx & 7;
            int grow = rowBase + r;
            float4 v = make_float4(0.f, 0.f, 0.f, 0.f);
            if (grow < NN) v = ((const float4*)(X + (size_t)grow * 128 + k0))[kk];
            float2* d = (float2*)&sX2[r * 32 + kk * 4];
            d[0] = make_float2(v.x, v.x);
            d[1] = make_float2(v.y, v.y);
            d[2] = make_float2(v.z, v.z);
            d[3] = make_float2(v.w, v.w);
        }
        __syncthreads();
        const ull* sW64 = (const ull*)sW;
#pragma unroll 4
        for (int k = 0; k < 32; k++) {
            ull w0 = sW64[k * 64 + lane * 2];
            ull w1 = sW64[k * 64 + lane * 2 + 1];
#pragma unroll
            for (int r = 0; r < 8; r++) {
                ull xv = sX2[(warp * 8 + r) * 32 + k];
                ffma2(acc2[r][0], xv, w0);
                ffma2(acc2[r][1], xv, w1);
            }
        }
        __syncthreads();
    }

    float4 av = make_float4(asr[lane*4], asr[lane*4+1], asr[lane*4+2], asr[lane*4+3]);
    float4 dv = make_float4(adr[lane*4], adr[lane*4+1], adr[lane*4+2], adr[lane*4+3]);
#pragma unroll
    for (int r = 0; r < 8; r++) {
        float4 acc = *(float4*)&acc2[r][0];
        int grow = rowBase + warp * 8 + r;
        float ps = acc.x * av.x + acc.y * av.y + acc.z * av.z + acc.w * av.w;
        float pd = acc.x * dv.x + acc.y * dv.y + acc.z * dv.z + acc.w * dv.w;
        __half2 p0 = __float22half2_rn(make_float2(acc.x, acc.y));
        __half2 p1 = __float22half2_rn(make_float2(acc.z, acc.w));
        uint2 hu;
        hu.x = *(unsigned*)&p0;
        hu.y = *(unsigned*)&p1;
        if (HEADS == 4) {
#pragma unroll
            for (int off = 4; off >= 1; off >>= 1) {
                ps += __shfl_xor_sync(0xffffffffu, ps, off);
                pd += __shfl_xor_sync(0xffffffffu, pd, off);
            }
            if (grow < NN) {
                g_h2[grow * 32 + lane] = hu;
                if ((lane & 7) == 0) {
                    g_as[grow * 4 + (lane >> 3)] = ps;
                    g_ad[grow * 4 + (lane >> 3)] = pd;
                }
            }
        } else {
#pragma unroll
            for (int off = 16; off >= 1; off >>= 1) {
                ps += __shfl_xor_sync(0xffffffffu, ps, off);
                pd += __shfl_xor_sync(0xffffffffu, pd, off);
            }
            if (grow < NN) {
                g_h2[grow * 32 + lane] = hu;
                if (lane == 0) { g_as[grow] = ps; g_ad[grow] = pd; }
            }
        }
    }
}

// ================= per-dst softmax aggregate (pipelined single pass) =====
// One warp per node; lanes split channels. Software-pipelined: group i+1's
// csr/alpha/h loads are issued before group i's math, keeping ~8 independent
// L2 loads in flight per warp (the loop was latency-bound, not BW-bound).

__device__ __forceinline__ float4 h4_to_f4(uint2 u) {
    __half2 p0 = *(__half2*)&u.x;
    __half2 p1 = *(__half2*)&u.y;
    float2 f0 = __half22float2(p0);
    float2 f1 = __half22float2(p1);
    return make_float4(f0.x, f0.y, f1.x, f1.y);
}

template <int HEADS, int OB>
__global__ __launch_bounds__(256) void k_aggr(
    const float* __restrict__ bias, float* __restrict__ outp)
{
    float* out = (OB == 2) ? outp : (OB == 0 ? (float*)g_t0 : (float*)g_t1);
    const int C = 128 / HEADS;
    int gw   = (blockIdx.x * blockDim.x + threadIdx.x) >> 5;
    int lane = threadIdx.x & 31;
    if (gw >= NN) return;
    int start = g_offsets[gw];
    int deg   = g_counts[gw];     // >= 1 (self-loop)

    const int hd  = (lane * 4) / C;
    const float adh = g_ad[gw * HEADS + hd];

    float sum = 0.f;
    float4 acc = make_float4(0.f, 0.f, 0.f, 0.f);

    int j = 0;
    if (deg >= 4) {
        // prologue: load group 0
        int i0 = g_csr[start], i1 = g_csr[start + 1],
            i2 = g_csr[start + 2], i3 = g_csr[start + 3];
        float e0 = g_as[i0 * HEADS + hd];
        float e1 = g_as[i1 * HEADS + hd];
        float e2 = g_as[i2 * HEADS + hd];
        float e3 = g_as[i3 * HEADS + hd];
        uint2 u0 = g_h2[(size_t)i0 * 32 + lane];
        uint2 u1 = g_h2[(size_t)i1 * 32 + lane];
        uint2 u2 = g_h2[(size_t)i2 * 32 + lane];
        uint2 u3 = g_h2[(size_t)i3 * 32 + lane];

        for (j = 4; j + 4 <= deg; j += 4) {
            // prefetch next group
            int n0 = g_csr[start + j],     n1 = g_csr[start + j + 1],
                n2 = g_csr[start + j + 2], n3 = g_csr[start + j + 3];
            float f0 = g_as[n0 * HEADS + hd];
            float f1 = g_as[n1 * HEADS + hd];
            float f2 = g_as[n2 * HEADS + hd];
            float f3 = g_as[n3 * HEADS + hd];
            uint2 v0 = g_h2[(size_t)n0 * 32 + lane];
            uint2 v1 = g_h2[(size_t)n1 * 32 + lane];
            uint2 v2 = g_h2[(size_t)n2 * 32 + lane];
            uint2 v3 = g_h2[(size_t)n3 * 32 + lane];
            // compute held group
            float t0 = e0 + adh; t0 = t0 > 0.f ? t0 : 0.2f * t0;
            float t1 = e1 + adh; t1 = t1 > 0.f ? t1 : 0.2f * t1;
            float t2 = e2 + adh; t2 = t2 > 0.f ? t2 : 0.2f * t2;
            float t3 = e3 + adh; t3 = t3 > 0.f ? t3 : 0.2f * t3;
            float a0 = __expf(t0), a1 = __expf(t1), a2 = __expf(t2), a3 = __expf(t3);
            sum += (a0 + a1) + (a2 + a3);
            float4 h0 = h4_to_f4(u0), h1 = h4_to_f4(u1), h2 = h4_to_f4(u2), h3 = h4_to_f4(u3);
            acc.x = fmaf(a0, h0.x, fmaf(a1, h1.x, fmaf(a2, h2.x, fmaf(a3, h3.x, acc.x))));
            acc.y = fmaf(a0, h0.y, fmaf(a1, h1.y, fmaf(a2, h2.y, fmaf(a3, h3.y, acc.y))));
            acc.z = fmaf(a0, h0.z, fmaf(a1, h1.z, fmaf(a2, h2.z, fmaf(a3, h3.z, acc.z))));
            acc.w = fmaf(a0, h0.w, fmaf(a1, h1.w, fmaf(a2, h2.w, fmaf(a3, h3.w, acc.w))));
            // rotate
            e0 = f0; e1 = f1; e2 = f2; e3 = f3;
            u0 = v0; u1 = v1; u2 = v2; u3 = v3;
        }
        // epilogue: compute held group
        float t0 = e0 + adh; t0 = t0 > 0.f ? t0 : 0.2f * t0;
        float t1 = e1 + adh; t1 = t1 > 0.f ? t1 : 0.2f * t1;
        float t2 = e2 + adh; t2 = t2 > 0.f ? t2 : 0.2f * t2;
        float t3 = e3 + adh; t3 = t3 > 0.f ? t3 : 0.2f * t3;
        float a0 = __expf(t0), a1 = __expf(t1), a2 = __expf(t2), a3 = __expf(t3);
        sum += (a0 + a1) + (a2 + a3);
        float4 h0 = h4_to_f4(u0), h1 = h4_to_f4(u1), h2 = h4_to_f4(u2), h3 = h4_to_f4(u3);
        acc.x = fmaf(a0, h0.x, fmaf(a1, h1.x, fmaf(a2, h2.x, fmaf(a3, h3.x, acc.x))));
        acc.y = fmaf(a0, h0.y, fmaf(a1, h1.y, fmaf(a2, h2.y, fmaf(a3, h3.y, acc.y))));
        acc.z = fmaf(a0, h0.z, fmaf(a1, h1.z, fmaf(a2, h2.z, fmaf(a3, h3.z, acc.z))));
        acc.w = fmaf(a0, h0.w, fmaf(a1, h1.w, fmaf(a2, h2.w, fmaf(a3, h3.w, acc.w))));
    }
    // tail
    for (; j < deg; j++) {
        int s0 = g_csr[start + j];
        float e = g_as[s0 * HEADS + hd] + adh;
        uint2 u = g_h2[(size_t)s0 * 32 + lane];
        e = e > 0.f ? e : 0.2f * e;
        float a = __expf(e);
        sum += a;
        float4 h = h4_to_f4(u);
        acc.x = fmaf(a, h.x, acc.x);
        acc.y = fmaf(a, h.y, acc.y);
        acc.z = fmaf(a, h.z, acc.z);
        acc.w = fmaf(a, h.w, acc.w);
    }

    float inv = 1.f / sum;
    float4 o;
    o.x = fmaxf(fmaf(acc.x, inv, bias[lane*4+0]), 0.f);
    o.y = fmaxf(fmaf(acc.y, inv, bias[lane*4+1]), 0.f);
    o.z = fmaxf(fmaf(acc.z, inv, bias[lane*4+2]), 0.f);
    o.w = fmaxf(fmaf(acc.w, inv, bias[lane*4+3]), 0.f);
    *(float4*)&out[(size_t)gw * 128 + lane * 4] = o;
}

// ================= launcher =================

extern "C" void kernel_launch(void* const* d_in, const int* in_sizes, int n_in,
                              void* d_out, int out_size)
{
    const float* x    = (const float*)d_in[0];
    const int*   ei32 = (const int*)d_in[1];
    const float* W0  = (const float*)d_in[2];
    const float* as0 = (const float*)d_in[3];
    const float* ad0 = (const float*)d_in[4];
    const float* b0  = (const float*)d_in[5];
    const float* W1  = (const float*)d_in[6];
    const float* as1 = (const float*)d_in[7];
    const float* ad1 = (const float*)d_in[8];
    const float* b1  = (const float*)d_in[9];
    const float* W2  = (const float*)d_in[10];
    const float* as2 = (const float*)d_in[11];
    const float* ad2 = (const float*)d_in[12];
    const float* b2  = (const float*)d_in[13];
    float* out = (float*)d_out;

    int gb = (NN + 63) / 64;
    int ab = (NN + 7) / 8;
    int nb = (NN + 511) / 512;

    cudaStream_t side;
    cudaStreamCreateWithFlags(&side, cudaStreamNonBlocking);
    cudaEvent_t evFork, evJoin;
    cudaEventCreateWithFlags(&evFork, cudaEventDisableTiming);
    cudaEventCreateWithFlags(&evJoin, cudaEventDisableTiming);

    cudaEventRecord(evFork, 0);
    cudaStreamWaitEvent(side, evFork, 0);

    // submission order matters for ncu -s: put gemm0 4th so it gets profiled
    k_detect <<<1, 64, 0, side>>>(ei32);
    k_zero   <<<(NN + 255) / 256, 256, 0, side>>>();
    k_hist   <<<(TE + 255) / 256, 256, 0, side>>>(ei32);
    k_gemm<4, 0><<<gb, 256>>>(x, W0, as0, ad0);          // main stream, overlaps CSR
    k_scanA  <<<nb, 512, 0, side>>>();
    k_scanB  <<<1, 128, 0, side>>>(nb);
    k_scanC  <<<nb, 512, 0, side>>>();
    k_scatter<<<(TE + 255) / 256, 256, 0, side>>>(ei32);
    cudaEventRecord(evJoin, side);
    cudaStreamWaitEvent(0, evJoin, 0);

    k_aggr<4, 0><<<ab, 256>>>(b0, nullptr);
    k_gemm<4, 1><<<gb, 256>>>(nullptr, W1, as1, ad1);
    k_aggr<4, 1><<<ab, 256>>>(b1, nullptr);
    k_gemm<1, 2><<<gb, 256>>>(nullptr, W2, as2, ad2);
    k_aggr<1, 2><<<ab, 256>>>(b2, out);

    cudaEventDestroy(evFork);
    cudaEventDestroy(evJoin);
    cudaStreamDestroy(side);
}

// round 9
// speedup vs baseline: 1.0837x; 1.0837x over previous
#include <cuda_runtime.h>
#include <cuda_fp16.h>

#define NN 50000
#define NE 800000
#define TE (NE + NN)

typedef unsigned long long ull;

// ---- scratch (static device globals: no allocation allowed) ----
__device__ int   g_is64;
__device__ int   g_counts[NN];
__device__ int   g_offsets[NN];
__device__ int   g_cursor[NN];
__device__ int   g_bsum[128];
__device__ int   g_csr[TE];
__device__ uint2 g_h2[NN * 32];    // per-layer GEMM output, fp16x4 per lane-slot
__device__ float g_t0[NN * 128];   // layer-0 output (fp32)
__device__ float g_t1[NN * 128];   // layer-1 output (fp32)
__device__ float g_as[NN * 4];     // alpha_src per node per head (fp32, exact)
__device__ float g_ad[NN * 4];     // alpha_dst per node per head (fp32, exact)

// packed-f32x2 FMA: d.xy = a.xy * b.xy + d.xy  (Blackwell; PTX-only encoding)
__device__ __forceinline__ void ffma2(ull& d, ull a, ull b) {
    asm("fma.rn.f32x2 %0, %1, %2, %0;" : "+l"(d) : "l"(a), "l"(b));
}
// pack {x, x} into a 64-bit register pair (2 MOVs on alu pipe; no LDS cost)
__device__ __forceinline__ ull dup2(float x) {
    ull r;
    asm("mov.b64 %0, {%1, %1};" : "=l"(r) : "f"(x));
    return r;
}

// ================= edge-index dtype detection (parallel) =================
__global__ void k_detect(const int* __restrict__ ei32) {
    int v = ei32[2 * threadIdx.x + 1];
    unsigned nz = __ballot_sync(0xffffffffu, v != 0);
    __shared__ unsigned s[2];
    if ((threadIdx.x & 31) == 0) s[threadIdx.x >> 5] = nz;
    __syncthreads();
    if (threadIdx.x == 0) g_is64 = ((s[0] | s[1]) == 0u) ? 1 : 0;
}

__device__ __forceinline__ int edge_at(const int* ei32, long long idx) {
    return g_is64 ? ei32[2 * idx] : ei32[idx];
}

// ================= CSR construction =================

__global__ void k_zero() {
    int i = blockIdx.x * blockDim.x + threadIdx.x;
    if (i < NN) g_counts[i] = 0;
}

__global__ void k_hist(const int* __restrict__ ei32) {
    int i = blockIdx.x * blockDim.x + threadIdx.x;
    if (i >= TE) return;
    int d = (i < NE) ? edge_at(ei32, (long long)NE + i) : (i - NE);
    if ((unsigned)d < NN) atomicAdd(&g_counts[d], 1);
}

__global__ void k_scanA() {
    __shared__ int s[512];
    int i = blockIdx.x * 512 + threadIdx.x;
    int v = (i < NN) ? g_counts[i] : 0;
    s[threadIdx.x] = v;
    __syncthreads();
    for (int off = 1; off < 512; off <<= 1) {
        int t = (threadIdx.x >= off) ? s[threadIdx.x - off] : 0;
        __syncthreads();
        s[threadIdx.x] += t;
        __syncthreads();
    }
    if (i < NN) g_offsets[i] = s[threadIdx.x] - v;
    if (threadIdx.x == 511) g_bsum[blockIdx.x] = s[511];
}

__global__ void k_scanB(int nb) {
    __shared__ int s[128];
    int t = threadIdx.x;
    int v = (t < nb) ? g_bsum[t] : 0;
    s[t] = v;
    __syncthreads();
    for (int off = 1; off < 128; off <<= 1) {
        int u = (t >= off) ? s[t - off] : 0;
        __syncthreads();
        s[t] += u;
        __syncthreads();
    }
    if (t < nb) g_bsum[t] = s[t] - v;
}

__global__ void k_scanC() {
    int i = blockIdx.x * 512 + threadIdx.x;
    if (i < NN) {
        int o = g_offsets[i] + g_bsum[blockIdx.x];
        g_offsets[i] = o;
        g_cursor[i]  = o;
    }
}

__global__ void k_scatter(const int* __restrict__ ei32) {
    int i = blockIdx.x * blockDim.x + threadIdx.x;
    if (i >= TE) return;
    int srcn, dstn;
    if (i < NE) {
        srcn = edge_at(ei32, i);
        dstn = edge_at(ei32, (long long)NE + i);
    } else {
        srcn = dstn = i - NE;
    }
    if ((unsigned)dstn >= NN || (unsigned)srcn >= NN) return;
    int pos = atomicAdd(&g_cursor[dstn], 1);
    if ((unsigned)pos < TE) g_csr[pos] = srcn;
}

// ================= GEMM (packed f32x2, X non-duplicated) =================
// h = X @ W. Block: 256 thr (8 warps); warp owns 8 rows, lane owns cols
// [4l,4l+4) as two f32x2 accumulators. X staged plain (LDS.32 broadcast, 1
// crossbar slot); the {x,x} FFMA2 operand is built with register MOVs.

template <int HEADS, int XB>
__global__ __launch_bounds__(256) void k_gemm(
    const float* __restrict__ Xin, const float* __restrict__ W,
    const float* __restrict__ asr, const float* __restrict__ adr)
{
    const float* X = (XB == 0) ? Xin : (XB == 1 ? (const float*)g_t0 : (const float*)g_t1);
    __shared__ float sW[32 * 128];    // 16 KB
    __shared__ float sX[64 * 32];     // 8 KB (plain)
    int tid  = threadIdx.x;
    int warp = tid >> 5, lane = tid & 31;
    int rowBase = blockIdx.x * 64;

    ull acc2[8][2];
#pragma unroll
    for (int r = 0; r < 8; r++) { acc2[r][0] = 0ull; acc2[r][1] = 0ull; }

    for (int k0 = 0; k0 < 128; k0 += 32) {
        for (int idx = tid; idx < 1024; idx += 256)
            ((float4*)sW)[idx] = ((const float4*)(W + k0 * 128))[idx];
        for (int idx = tid; idx < 512; idx += 256) {
            int r = idx >> 3, kk = idx & 7;
            int grow = rowBase + r;
            float4 v = make_float4(0.f, 0.f, 0.f, 0.f);
            if (grow < NN) v = ((const float4*)(X + (size_t)grow * 128 + k0))[kk];
            ((float4*)sX)[idx] = v;
        }
        __syncthreads();
        const ull* sW64 = (const ull*)sW;
#pragma unroll 4
        for (int k = 0; k < 32; k++) {
            ull w0 = sW64[k * 64 + lane * 2];
            ull w1 = sW64[k * 64 + lane * 2 + 1];
#pragma unroll
            for (int r = 0; r < 8; r++) {
                ull xx = dup2(sX[(warp * 8 + r) * 32 + k]);
                ffma2(acc2[r][0], xx, w0);
                ffma2(acc2[r][1], xx, w1);
            }
        }
        __syncthreads();
    }

    float4 av = make_float4(asr[lane*4], asr[lane*4+1], asr[lane*4+2], asr[lane*4+3]);
    float4 dv = make_float4(adr[lane*4], adr[lane*4+1], adr[lane*4+2], adr[lane*4+3]);
#pragma unroll
    for (int r = 0; r < 8; r++) {
        float4 acc = *(float4*)&acc2[r][0];
        int grow = rowBase + warp * 8 + r;
        float ps = acc.x * av.x + acc.y * av.y + acc.z * av.z + acc.w * av.w;
        float pd = acc.x * dv.x + acc.y * dv.y + acc.z * dv.z + acc.w * dv.w;
        __half2 p0 = __float22half2_rn(make_float2(acc.x, acc.y));
        __half2 p1 = __float22half2_rn(make_float2(acc.z, acc.w));
        uint2 hu;
        hu.x = *(unsigned*)&p0;
        hu.y = *(unsigned*)&p1;
        if (HEADS == 4) {
#pragma unroll
            for (int off = 4; off >= 1; off >>= 1) {
                ps += __shfl_xor_sync(0xffffffffu, ps, off);
                pd += __shfl_xor_sync(0xffffffffu, pd, off);
            }
            if (grow < NN) {
                g_h2[grow * 32 + lane] = hu;
                if ((lane & 7) == 0) {
                    g_as[grow * 4 + (lane >> 3)] = ps;
                    g_ad[grow * 4 + (lane >> 3)] = pd;
                }
            }
        } else {
#pragma unroll
            for (int off = 16; off >= 1; off >>= 1) {
                ps += __shfl_xor_sync(0xffffffffu, ps, off);
                pd += __shfl_xor_sync(0xffffffffu, pd, off);
            }
            if (grow < NN) {
                g_h2[grow * 32 + lane] = hu;
                if (lane == 0) { g_as[grow] = ps; g_ad[grow] = pd; }
            }
        }
    }
}

// ================= per-dst softmax aggregate (single pass, unroll 4) =====

__device__ __forceinline__ float4 h4_to_f4(uint2 u) {
    __half2 p0 = *(__half2*)&u.x;
    __half2 p1 = *(__half2*)&u.y;
    float2 f0 = __half22float2(p0);
    float2 f1 = __half22float2(p1);
    return make_float4(f0.x, f0.y, f1.x, f1.y);
}

template <int HEADS, int OB>
__global__ __launch_bounds__(256) void k_aggr(
    const float* __restrict__ bias, float* __restrict__ outp)
{
    float* out = (OB == 2) ? outp : (OB == 0 ? (float*)g_t0 : (float*)g_t1);
    const int C = 128 / HEADS;
    int gw   = (blockIdx.x * blockDim.x + threadIdx.x) >> 5;
    int lane = threadIdx.x & 31;
    if (gw >= NN) return;
    int start = g_offsets[gw];
    int deg   = g_counts[gw];     // >= 1 (self-loop)

    const int hd  = (lane * 4) / C;
    const float adh = g_ad[gw * HEADS + hd];

    float sum = 0.f;
    float4 acc = make_float4(0.f, 0.f, 0.f, 0.f);

    int j = 0;
    for (; j + 4 <= deg; j += 4) {
        int s0 = g_csr[start + j];
        int s1 = g_csr[start + j + 1];
        int s2 = g_csr[start + j + 2];
        int s3 = g_csr[start + j + 3];
        float e0 = g_as[s0 * HEADS + hd] + adh;
        float e1 = g_as[s1 * HEADS + hd] + adh;
        float e2 = g_as[s2 * HEADS + hd] + adh;
        float e3 = g_as[s3 * HEADS + hd] + adh;
        uint2 u0 = g_h2[(size_t)s0 * 32 + lane];
        uint2 u1 = g_h2[(size_t)s1 * 32 + lane];
        uint2 u2 = g_h2[(size_t)s2 * 32 + lane];
        uint2 u3 = g_h2[(size_t)s3 * 32 + lane];
        e0 = e0 > 0.f ? e0 : 0.2f * e0;
        e1 = e1 > 0.f ? e1 : 0.2f * e1;
        e2 = e2 > 0.f ? e2 : 0.2f * e2;
        e3 = e3 > 0.f ? e3 : 0.2f * e3;
        float a0 = __expf(e0), a1 = __expf(e1), a2 = __expf(e2), a3 = __expf(e3);
        sum += (a0 + a1) + (a2 + a3);
        float4 hv0 = h4_to_f4(u0);
        float4 hv1 = h4_to_f4(u1);
        float4 hv2 = h4_to_f4(u2);
        float4 hv3 = h4_to_f4(u3);
        acc.x = fmaf(a0, hv0.x, fmaf(a1, hv1.x, fmaf(a2, hv2.x, fmaf(a3, hv3.x, acc.x))));
        acc.y = fmaf(a0, hv0.y, fmaf(a1, hv1.y, fmaf(a2, hv2.y, fmaf(a3, hv3.y, acc.y))));
        acc.z = fmaf(a0, hv0.z, fmaf(a1, hv1.z, fmaf(a2, hv2.z, fmaf(a3, hv3.z, acc.z))));
        acc.w = fmaf(a0, hv0.w, fmaf(a1, hv1.w, fmaf(a2, hv2.w, fmaf(a3, hv3.w, acc.w))));
    }
    for (; j < deg; j++) {
        int s0 = g_csr[start + j];
        float e0 = g_as[s0 * HEADS + hd] + adh;
        uint2 u0 = g_h2[(size_t)s0 * 32 + lane];
        e0 = e0 > 0.f ? e0 : 0.2f * e0;
        float a0 = __expf(e0);
        sum += a0;
        float4 hv0 = h4_to_f4(u0);
        acc.x = fmaf(a0, hv0.x, acc.x);
        acc.y = fmaf(a0, hv0.y, acc.y);
        acc.z = fmaf(a0, hv0.z, acc.z);
        acc.w = fmaf(a0, hv0.w, acc.w);
    }

    float inv = 1.f / sum;
    float4 o;
    o.x = fmaxf(fmaf(acc.x, inv, bias[lane*4+0]), 0.f);
    o.y = fmaxf(fmaf(acc.y, inv, bias[lane*4+1]), 0.f);
    o.z = fmaxf(fmaf(acc.z, inv, bias[lane*4+2]), 0.f);
    o.w = fmaxf(fmaf(acc.w, inv, bias[lane*4+3]), 0.f);
    *(float4*)&out[(size_t)gw * 128 + lane * 4] = o;
}

// ================= launcher =================

extern "C" void kernel_launch(void* const* d_in, const int* in_sizes, int n_in,
                              void* d_out, int out_size)
{
    const float* x    = (const float*)d_in[0];
    const int*   ei32 = (const int*)d_in[1];
    const float* W0  = (const float*)d_in[2];
    const float* as0 = (const float*)d_in[3];
    const float* ad0 = (const float*)d_in[4];
    const float* b0  = (const float*)d_in[5];
    const float* W1  = (const float*)d_in[6];
    const float* as1 = (const float*)d_in[7];
    const float* ad1 = (const float*)d_in[8];
    const float* b1  = (const float*)d_in[9];
    const float* W2  = (const float*)d_in[10];
    const float* as2 = (const float*)d_in[11];
    const float* ad2 = (const float*)d_in[12];
    const float* b2  = (const float*)d_in[13];
    float* out = (float*)d_out;

    int gb = (NN + 63) / 64;
    int ab = (NN + 7) / 8;
    int nb = (NN + 511) / 512;

    cudaStream_t side;
    cudaStreamCreateWithFlags(&side, cudaStreamNonBlocking);
    cudaEvent_t evFork, evJoin;
    cudaEventCreateWithFlags(&evFork, cudaEventDisableTiming);
    cudaEventCreateWithFlags(&evJoin, cudaEventDisableTiming);

    cudaEventRecord(evFork, 0);
    cudaStreamWaitEvent(side, evFork, 0);

    // submission order matters for ncu -s: keep gemm0 4th so it gets profiled
    k_detect <<<1, 64, 0, side>>>(ei32);
    k_zero   <<<(NN + 255) / 256, 256, 0, side>>>();
    k_hist   <<<(TE + 255) / 256, 256, 0, side>>>(ei32);
    k_gemm<4, 0><<<gb, 256>>>(x, W0, as0, ad0);          // main stream, overlaps CSR
    k_scanA  <<<nb, 512, 0, side>>>();
    k_scanB  <<<1, 128, 0, side>>>(nb);
    k_scanC  <<<nb, 512, 0, side>>>();
    k_scatter<<<(TE + 255) / 256, 256, 0, side>>>(ei32);
    cudaEventRecord(evJoin, side);
    cudaStreamWaitEvent(0, evJoin, 0);

    k_aggr<4, 0><<<ab, 256>>>(b0, nullptr);
    k_gemm<4, 1><<<gb, 256>>>(nullptr, W1, as1, ad1);
    k_aggr<4, 1><<<ab, 256>>>(b1, nullptr);
    k_gemm<1, 2><<<gb, 256>>>(nullptr, W2, as2, ad2);
    k_aggr<1, 2><<<ab, 256>>>(b2, out);

    cudaEventDestroy(evFork);
    cudaEventDestroy(evJoin);
    cudaStreamDestroy(side);
}